// round 13
// baseline (speedup 1.0000x reference)
#include <cuda_runtime.h>
#include <math.h>

#define Bn 16
#define Sn 4096
#define Dn 256
#define Nn 16
#define Ln 64
#define Cn (Sn / Ln)   // 64 chunks
#define DTc 1e-4f
#define EPSc 1e-5f
#define X1S 132        // phase1 staged half-row stride (16B-aligned, conflict-free)
#define YS 260         // phase3 y/u buffer stride (16B-aligned, conflict-free)
#define WSTRIDE 68

// Static scratch. g_H layout: [b][c][t][n] (t-major: phase3 loads with no transpose).
__device__ float g_H[(size_t)Bn * Cn * Ln * Nn];   // 4 MB
__device__ float g_hend[Bn * Cn * Nn];
__device__ float g_hstart[Bn * Cn * Nn];

// Packed fp32 pair FMA (FFMA2, rt=1): acc.{lo,hi} += u.{lo,hi} * b.{lo,hi}.
// Exact per-lane fp32 .rn semantics.
__device__ __forceinline__ void ffma2(unsigned long long& acc,
                                      unsigned long long u,
                                      unsigned long long b) {
    asm("fma.rn.f32x2 %0, %1, %2, %0;" : "+l"(acc) : "l"(u), "l"(b));
}
union U64F2 { unsigned long long u; float2 f; };
__device__ __forceinline__ float pairsum(unsigned long long v) {
    U64F2 c; c.u = v; return c.f.x + c.f.y;
}

// ---------------------------------------------------------------------------
// Phase 1: per (batch, chunk). W = B_d @ U over D=256 in two 128-wide passes,
// FFMA2 inner loop (even/odd-d partial sums), depth-2 smem prefetch.
// Then warp-parallel Kogge-Stone scan over L=64, store H ([t][n]) + hend.
// ---------------------------------------------------------------------------
__global__ __launch_bounds__(256, 3) void s4_phase1(const float* __restrict__ x,
                                                    const float* __restrict__ A,
                                                    const float* __restrict__ Bm) {
    extern __shared__ float smem[];
    float (*Xh)[X1S]     = (float(*)[X1S])smem;                       // 64 x 132
    float (*Bs)[Dn]      = (float(*)[Dn])(smem + Ln * X1S);           // 16 x 256
    float (*Ws)[WSTRIDE] = (float(*)[WSTRIDE])(smem + Ln * X1S + Nn * Dn);
    float* Ad            = smem + Ln * X1S + Nn * Dn + Nn * WSTRIDE;

    int blk = blockIdx.x;
    int b = blk / Cn, c = blk % Cn;
    int tid = threadIdx.x;

    // B_d = DT * Bm (full), once.
    float* bsf = &Bs[0][0];
    #pragma unroll
    for (int k = 0; k < 16; k++) {
        int i = tid + k * 256;
        bsf[i] = DTc * Bm[i];
    }
    if (tid < Nn) Ad[tid] = (float)exp(-(double)DTc * fabs((double)A[tid]));

    const float4* xg = (const float4*)(x + ((size_t)b * Sn + (size_t)c * Ln) * Dn);
    int t  = tid & 63;
    int n0 = (tid >> 6) * 4;
    unsigned long long A0 = 0ull, A1 = 0ull, A2 = 0ull, A3 = 0ull;

    #pragma unroll
    for (int p = 0; p < 2; p++) {
        __syncthreads();   // Bs ready (p=0) / prior GEMM reads done (p=1)
        // Stage half of x chunk: cols [128p, 128p+128).
        #pragma unroll
        for (int k = 0; k < 8; k++) {
            int i4 = tid + k * 256;
            int tt = i4 >> 5, d4 = i4 & 31;
            *(float4*)&Xh[tt][d4 * 4] = xg[tt * 64 + p * 32 + d4];
        }
        __syncthreads();

        // GEMM half: 32 granules of 4 d. FFMA2 x8 per granule, depth-2 prefetch.
        const ulonglong2* up = (const ulonglong2*)&Xh[t][0];
        const ulonglong2* bq = (const ulonglong2*)&Bs[n0][0] + p * 32;  // rows 64 apart
        ulonglong2 u0v = up[0];
        ulonglong2 b00 = bq[0], b10 = bq[64], b20 = bq[128], b30 = bq[192];
        ulonglong2 u1v = up[1];
        ulonglong2 b01 = bq[1], b11 = bq[65], b21 = bq[129], b31 = bq[193];
        #pragma unroll 8
        for (int j = 0; j < 32; j++) {
            int jn = (j + 2 < 32) ? j + 2 : j;
            ulonglong2 u2v = up[jn];
            ulonglong2 b02 = bq[jn],      b12 = bq[64 + jn];
            ulonglong2 b22 = bq[128 + jn], b32 = bq[192 + jn];
            ffma2(A0, u0v.x, b00.x); ffma2(A0, u0v.y, b00.y);
            ffma2(A1, u0v.x, b10.x); ffma2(A1, u0v.y, b10.y);
            ffma2(A2, u0v.x, b20.x); ffma2(A2, u0v.y, b20.y);
            ffma2(A3, u0v.x, b30.x); ffma2(A3, u0v.y, b30.y);
            u0v = u1v; b00 = b01; b10 = b11; b20 = b21; b30 = b31;
            u1v = u2v; b01 = b02; b11 = b12; b21 = b22; b31 = b32;
        }
    }
    Ws[n0 + 0][t] = pairsum(A0);
    Ws[n0 + 1][t] = pairsum(A1);
    Ws[n0 + 2][t] = pairsum(A2);
    Ws[n0 + 3][t] = pairsum(A3);
    __syncthreads();

    // Warp-parallel scan: warp w handles n = w and n = w + 8.
    {
        int w = tid >> 5, lane = tid & 31;
        #pragma unroll
        for (int rep = 0; rep < 2; rep++) {
            int n = w + rep * 8;
            float a1 = Ad[n];
            float a2 = a1 * a1, a4 = a2 * a2, a8 = a4 * a4, a16 = a8 * a8;
            // half 0 (t = 0..31): Kogge-Stone linear-recurrence scan
            float h = Ws[n][lane];
            float v;
            v = __shfl_up_sync(0xffffffffu, h, 1);  if (lane >= 1)  h = fmaf(a1,  v, h);
            v = __shfl_up_sync(0xffffffffu, h, 2);  if (lane >= 2)  h = fmaf(a2,  v, h);
            v = __shfl_up_sync(0xffffffffu, h, 4);  if (lane >= 4)  h = fmaf(a4,  v, h);
            v = __shfl_up_sync(0xffffffffu, h, 8);  if (lane >= 8)  h = fmaf(a8,  v, h);
            v = __shfl_up_sync(0xffffffffu, h, 16); if (lane >= 16) h = fmaf(a16, v, h);
            float h31 = __shfl_sync(0xffffffffu, h, 31);
            Ws[n][lane] = h;
            // half 1 (t = 32..63)
            float g2 = Ws[n][lane + 32];
            v = __shfl_up_sync(0xffffffffu, g2, 1);  if (lane >= 1)  g2 = fmaf(a1,  v, g2);
            v = __shfl_up_sync(0xffffffffu, g2, 2);  if (lane >= 2)  g2 = fmaf(a2,  v, g2);
            v = __shfl_up_sync(0xffffffffu, g2, 4);  if (lane >= 4)  g2 = fmaf(a4,  v, g2);
            v = __shfl_up_sync(0xffffffffu, g2, 8);  if (lane >= 8)  g2 = fmaf(a8,  v, g2);
            v = __shfl_up_sync(0xffffffffu, g2, 16); if (lane >= 16) g2 = fmaf(a16, v, g2);
            // carry: + a^(lane+1) * h31
            float al = a1;
            if (lane & 1)  al *= a1;
            if (lane & 2)  al *= a2;
            if (lane & 4)  al *= a4;
            if (lane & 8)  al *= a8;
            if (lane & 16) al *= a16;
            g2 = fmaf(al, h31, g2);
            Ws[n][lane + 32] = g2;
            if (lane == 31) g_hend[(b * Cn + c) * Nn + n] = g2;
        }
    }
    __syncthreads();

    // Copy-out H in [t][n] order (coalesced global).
    size_t base = ((size_t)(b * Cn + c)) * Ln * Nn;
    #pragma unroll
    for (int k = 0; k < 4; k++) {
        int i = tid + k * 256;
        int tt = i >> 4, n = i & 15;
        g_H[base + i] = Ws[n][tt];
    }
}

// ---------------------------------------------------------------------------
// Phase 2: scan across chunks. One block, 256 threads = (b, n).
// ---------------------------------------------------------------------------
__global__ __launch_bounds__(256) void s4_phase2(const float* __restrict__ A) {
    int tid = threadIdx.x;
    int b = tid >> 4, n = tid & 15;
    float a = (float)exp(-(double)DTc * fabs((double)A[n]));
    float aL = a;
    #pragma unroll
    for (int i = 0; i < 6; i++) aL *= aL;   // a^64

    float he[Cn];
    #pragma unroll
    for (int c = 0; c < Cn; c++) he[c] = g_hend[(b * Cn + c) * Nn + n];
    float s = 0.f;
    #pragma unroll
    for (int c = 0; c < Cn; c++) {
        g_hstart[(b * Cn + c) * Nn + n] = s;
        s = fmaf(aL, s, he[c]);
    }
}

// ---------------------------------------------------------------------------
// Phase 3: per (batch, chunk). x staged to smem (u), parallel correction of H,
// GEMM2 with FFMA2 (y written in-place over u), LayerNorm, write out.
// ---------------------------------------------------------------------------
__global__ __launch_bounds__(256, 3) void s4_phase3(const float* __restrict__ x,
                                                    const float* __restrict__ A,
                                                    const float* __restrict__ Cm,
                                                    const float* __restrict__ Dv,
                                                    const float* __restrict__ gamma,
                                                    const float* __restrict__ beta,
                                                    float* __restrict__ out) {
    extern __shared__ float smem[];
    float (*Ys)[YS] = (float(*)[YS])smem;                    // 64 x 260 (u, then y)
    float (*Ht)[Nn] = (float(*)[Nn])(smem + Ln * YS);        // 64 x 16 [t][n]

    int blk = blockIdx.x;
    int b = blk / Cn, c = blk % Cn;
    int tid = threadIdx.x;

    // Stage x chunk into Ys (bulk, MLP=16, conflict-free float4 phases).
    const float4* xg = (const float4*)(x + ((size_t)b * Sn + (size_t)c * Ln) * Dn);
    #pragma unroll
    for (int k = 0; k < 16; k++) {
        int i4 = tid + k * 256;
        int t = i4 >> 6, d4 = i4 & 63;
        *(float4*)&Ys[t][d4 * 4] = xg[i4];
    }
    // Load local H ([t][n]): one float4 per thread, conflict-free.
    {
        const float4* hg = (const float4*)(g_H + ((size_t)(b * Cn + c)) * Ln * Nn);
        ((float4*)&Ht[0][0])[tid] = hg[tid];
    }
    __syncthreads();

    // Parallel correction: all 1024 (t,n) cells, 4 per thread (same n).
    {
        int n  = tid & 15;
        int tt = tid >> 4;          // 0..15, element rows tt, tt+16, tt+32, tt+48
        float a1 = (float)exp(-(double)DTc * fabs((double)A[n]));
        float s  = g_hstart[(b * Cn + c) * Nn + n];
        float a2 = a1 * a1, a4 = a2 * a2, a8 = a4 * a4;
        float a16 = a8 * a8, a32 = a16 * a16;
        #pragma unroll
        for (int k = 0; k < 4; k++) {
            int t = tt + k * 16;
            int e = t + 1;          // 1..64
            float p = 1.f;
            if (e & 1)  p *= a1;
            if (e & 2)  p *= a2;
            if (e & 4)  p *= a4;
            if (e & 8)  p *= a8;
            if (e & 16) p *= a16;
            if (e & 32) p *= a32;
            if (e == 64) p = a32 * a32;
            float vv = fmaf(p, s, Ht[t][n]);
            vv = fminf(fmaxf(vv, -10.f), 10.f);
            Ht[t][n] = vv;
        }
    }
    __syncthreads();

    // GEMM2: thread handles columns d and d+128 for its 32-row t-half.
    // FFMA2 over natural n-pairs; Ht row = 4 x 16B broadcasts.
    int d  = tid & 127;
    int t0 = (tid >> 7) * 32;
    const ulonglong2* cp = (const ulonglong2*)(Cm + d * Nn);          // 4 UL2
    const ulonglong2* ep = (const ulonglong2*)(Cm + (d + 128) * Nn);
    ulonglong2 c0 = cp[0], c1 = cp[1], c2 = cp[2], c3 = cp[3];
    ulonglong2 e0 = ep[0], e1 = ep[1], e2 = ep[2], e3 = ep[3];
    float dv0 = Dv[d], dv1 = Dv[d + 128];

    #pragma unroll 4
    for (int t = t0; t < t0 + 32; t++) {
        const ulonglong2* hp = (const ulonglong2*)&Ht[t][0];
        ulonglong2 h0 = hp[0], h1 = hp[1], h2 = hp[2], h3 = hp[3];
        unsigned long long p0 = 0ull, p1 = 0ull, q0 = 0ull, q1 = 0ull;
        ffma2(p0, h0.x, c0.x); ffma2(p1, h0.y, c0.y);
        ffma2(p0, h1.x, c1.x); ffma2(p1, h1.y, c1.y);
        ffma2(p0, h2.x, c2.x); ffma2(p1, h2.y, c2.y);
        ffma2(p0, h3.x, c3.x); ffma2(p1, h3.y, c3.y);
        ffma2(q0, h0.x, e0.x); ffma2(q1, h0.y, e0.y);
        ffma2(q0, h1.x, e1.x); ffma2(q1, h1.y, e1.y);
        ffma2(q0, h2.x, e2.x); ffma2(q1, h2.y, e2.y);
        ffma2(q0, h3.x, e3.x); ffma2(q1, h3.y, e3.y);
        float u0 = Ys[t][d], u1 = Ys[t][d + 128];
        float y0 = fmaf(u0, dv0, pairsum(p0) + pairsum(p1));
        float y1 = fmaf(u1, dv1, pairsum(q0) + pairsum(q1));
        y0 = fminf(fmaxf(y0, -10.f), 10.f);
        y1 = fminf(fmaxf(y1, -10.f), 10.f);
        Ys[t][d] = y0;
        Ys[t][d + 128] = y1;
    }
    __syncthreads();

    // LayerNorm: one warp per 8 rows.
    int w = tid >> 5, lane = tid & 31;
    float g[8], bt[8];
    #pragma unroll
    for (int k = 0; k < 8; k++) {
        g[k]  = gamma[lane + 32 * k];
        bt[k] = beta[lane + 32 * k];
    }
    #pragma unroll
    for (int r = 0; r < 8; r++) {
        int t = w * 8 + r;
        float yv[8];
        float s1 = 0.f, s2 = 0.f;
        #pragma unroll
        for (int k = 0; k < 8; k++) {
            float y = Ys[t][lane + 32 * k];
            yv[k] = y;
            s1 += y;
            s2 = fmaf(y, y, s2);
        }
        #pragma unroll
        for (int off = 16; off > 0; off >>= 1) {
            s1 += __shfl_xor_sync(0xffffffffu, s1, off);
            s2 += __shfl_xor_sync(0xffffffffu, s2, off);
        }
        float mu  = s1 * (1.f / Dn);
        float var = s2 * (1.f / Dn) - mu * mu;
        float rs  = rsqrtf(var + EPSc);
        float* orow = out + ((size_t)b * Sn + (size_t)(c * Ln + t)) * Dn;
        #pragma unroll
        for (int k = 0; k < 8; k++) {
            orow[lane + 32 * k] = fmaf((yv[k] - mu) * rs, g[k], bt[k]);
        }
    }
}

extern "C" void kernel_launch(void* const* d_in, const int* in_sizes, int n_in,
                              void* d_out, int out_size) {
    (void)in_sizes; (void)n_in; (void)out_size;
    const float* x     = (const float*)d_in[0];
    const float* A     = (const float*)d_in[1];
    const float* Bm    = (const float*)d_in[2];
    const float* Cm    = (const float*)d_in[3];
    const float* Dv    = (const float*)d_in[4];
    const float* gamma = (const float*)d_in[5];
    const float* beta  = (const float*)d_in[6];
    float* out = (float*)d_out;

    const int smem1 = (Ln * X1S + Nn * Dn + Nn * WSTRIDE + Nn) * 4;   // ~54.6 KB
    const int smem3 = (Ln * YS + Ln * Nn) * 4;                        // ~70.7 KB
    cudaFuncSetAttribute(s4_phase1, cudaFuncAttributeMaxDynamicSharedMemorySize, smem1);
    cudaFuncSetAttribute(s4_phase3, cudaFuncAttributeMaxDynamicSharedMemorySize, smem3);

    s4_phase1<<<Bn * Cn, 256, smem1>>>(x, A, Bm);
    s4_phase2<<<1, 256>>>(A);
    s4_phase3<<<Bn * Cn, 256, smem3>>>(x, A, Cm, Dv, gamma, beta, out);
}

// round 16
// speedup vs baseline: 1.1916x; 1.1916x over previous
#include <cuda_runtime.h>
#include <math.h>

#define Bn 16
#define Sn 4096
#define Dn 256
#define Nn 16
#define Ln 64
#define Cn (Sn / Ln)   // 64 chunks
#define DTc 1e-4f
#define EPSc 1e-5f
#define XS 260         // staged x row stride (16B aligned, conflict-free f4/scalar)
#define BS 20          // Bst row stride (16B aligned, pairs adjacent)
#define WS 68          // W row stride

// Static scratch. g_H layout: [b][c][t][n].
__device__ float g_H[(size_t)Bn * Cn * Ln * Nn];   // 4 MB
__device__ float g_hend[Bn * Cn * Nn];
__device__ float g_hstart[Bn * Cn * Nn];

// FFMA2: acc.{lo,hi} += u.{lo,hi} * b.{lo,hi} (exact per-lane fp32 .rn).
__device__ __forceinline__ void ffma2(unsigned long long& acc,
                                      unsigned long long u,
                                      unsigned long long b) {
    asm("fma.rn.f32x2 %0, %1, %2, %0;" : "+l"(acc) : "l"(u), "l"(b));
}
__device__ __forceinline__ unsigned long long dup2(float v) {
    unsigned long long r;
    asm("mov.b64 %0, {%1, %1};" : "=l"(r) : "f"(v));
    return r;
}
__device__ __forceinline__ float lo2(unsigned long long v) {
    float a, b; asm("mov.b64 {%0, %1}, %2;" : "=f"(a), "=f"(b) : "l"(v)); return a;
}
__device__ __forceinline__ float hi2(unsigned long long v) {
    float a, b; asm("mov.b64 {%0, %1}, %2;" : "=f"(a), "=f"(b) : "l"(v)); return b;
}
__device__ __forceinline__ void cpasync16(void* s, const void* g) {
    unsigned sa = (unsigned)__cvta_generic_to_shared(s);
    asm volatile("cp.async.cg.shared.global [%0], [%1], 16;" :: "r"(sa), "l"(g));
}
__device__ __forceinline__ void cpasync_commit() {
    asm volatile("cp.async.commit_group;");
}
__device__ __forceinline__ void cpasync_wait0() {
    asm volatile("cp.async.wait_group 0;");
}

// ---------------------------------------------------------------------------
// Phase 1: per (batch, chunk). W = B_d @ U over D=256.
// Tiling: 256 thr = 4 d-quarters x 2 n-octets x 32 lanes; thread covers
// t in {lane, lane+32}, 8 n, 64 d. B staged transposed [d][n] (stride 20) so
// FFMA2 n-pairs are adjacent and reads are warp-broadcast. Partials reduced
// across d-quarters in smem, warp-parallel Kogge-Stone scan, store H + hend.
// ---------------------------------------------------------------------------
__global__ __launch_bounds__(256, 2) void s4_phase1(const float* __restrict__ x,
                                                    const float* __restrict__ A,
                                                    const float* __restrict__ Bm) {
    extern __shared__ float smem[];
    float (*Xs)[XS]      = (float(*)[XS])smem;                       // 64 x 260
    float* BstF          = smem + Ln * XS;                           // 256 x 20
    float (*Wp)[Nn][WS]  = (float(*)[Nn][WS])(smem + Ln * XS + Dn * BS); // [4][16][68]
    float* Ad            = smem + Ln * XS + Dn * BS + 4 * Nn * WS;

    int blk = blockIdx.x;
    int b = blk / Cn, c = blk % Cn;
    int tid = threadIdx.x;

    // Async-stage x chunk (64KB) into padded smem rows.
    const float4* xg = (const float4*)(x + ((size_t)b * Sn + (size_t)c * Ln) * Dn);
    #pragma unroll
    for (int k = 0; k < 16; k++) {
        int i4 = tid + k * 256;
        int t = i4 >> 6, d4 = i4 & 63;
        cpasync16(&Xs[t][d4 * 4], xg + i4);
    }
    cpasync_commit();

    // Stage B transposed+scaled: Bst[d][n] = DT * Bm[n][d]. Coalesced LDG;
    // STS is 4-way conflicted (stride 20), one-time cost.
    #pragma unroll
    for (int k = 0; k < 16; k++) {
        int i = tid + k * 256;
        int n = i >> 8, d = i & 255;
        BstF[d * BS + n] = DTc * Bm[i];
    }
    if (tid < Nn) Ad[tid] = (float)exp(-(double)DTc * fabs((double)A[tid]));
    cpasync_wait0();
    __syncthreads();

    // GEMM1.
    int lane = tid & 31;
    int nt   = (tid >> 5) & 1;    // n-octet
    int dq   = tid >> 6;          // d-quarter
    int n0   = nt * 8;
    const float4* xa = (const float4*)&Xs[lane][0] + dq * 16;
    const float4* xb = (const float4*)&Xs[lane + 32][0] + dq * 16;

    unsigned long long A0 = 0, A1 = 0, A2 = 0, A3 = 0;   // t = lane,   n0..n0+7
    unsigned long long B0 = 0, B1 = 0, B2 = 0, B3 = 0;   // t = lane+32
    #pragma unroll 4
    for (int g = 0; g < 16; g++) {
        float4 ua = xa[g];
        float4 ub = xb[g];
        unsigned long long pa0 = dup2(ua.x), pa1 = dup2(ua.y),
                           pa2 = dup2(ua.z), pa3 = dup2(ua.w);
        unsigned long long pb0 = dup2(ub.x), pb1 = dup2(ub.y),
                           pb2 = dup2(ub.z), pb3 = dup2(ub.w);
        #pragma unroll
        for (int j = 0; j < 4; j++) {
            int r = dq * 64 + 4 * g + j;
            const ulonglong2* bp = (const ulonglong2*)(BstF + r * BS + n0);
            ulonglong2 v0 = bp[0];   // n0 .. n0+3
            ulonglong2 v1 = bp[1];   // n0+4 .. n0+7
            unsigned long long pa = (j == 0) ? pa0 : (j == 1) ? pa1 : (j == 2) ? pa2 : pa3;
            unsigned long long pb = (j == 0) ? pb0 : (j == 1) ? pb1 : (j == 2) ? pb2 : pb3;
            ffma2(A0, pa, v0.x); ffma2(A1, pa, v0.y);
            ffma2(A2, pa, v1.x); ffma2(A3, pa, v1.y);
            ffma2(B0, pb, v0.x); ffma2(B1, pb, v0.y);
            ffma2(B2, pb, v1.x); ffma2(B3, pb, v1.y);
        }
    }
    // Write partials: Wp[dq][n][t] (lane-stride-1, conflict-free).
    Wp[dq][n0 + 0][lane] = lo2(A0); Wp[dq][n0 + 1][lane] = hi2(A0);
    Wp[dq][n0 + 2][lane] = lo2(A1); Wp[dq][n0 + 3][lane] = hi2(A1);
    Wp[dq][n0 + 4][lane] = lo2(A2); Wp[dq][n0 + 5][lane] = hi2(A2);
    Wp[dq][n0 + 6][lane] = lo2(A3); Wp[dq][n0 + 7][lane] = hi2(A3);
    Wp[dq][n0 + 0][lane + 32] = lo2(B0); Wp[dq][n0 + 1][lane + 32] = hi2(B0);
    Wp[dq][n0 + 2][lane + 32] = lo2(B1); Wp[dq][n0 + 3][lane + 32] = hi2(B1);
    Wp[dq][n0 + 4][lane + 32] = lo2(B2); Wp[dq][n0 + 5][lane + 32] = hi2(B2);
    Wp[dq][n0 + 6][lane + 32] = lo2(B3); Wp[dq][n0 + 7][lane + 32] = hi2(B3);
    __syncthreads();

    // Reduce d-quarters into Wp[0].
    #pragma unroll
    for (int k = 0; k < 4; k++) {
        int i = tid + k * 256;
        int n = i >> 6, t = i & 63;
        Wp[0][n][t] = (Wp[0][n][t] + Wp[1][n][t]) + (Wp[2][n][t] + Wp[3][n][t]);
    }
    __syncthreads();

    // Warp-parallel scan: warp w handles n = w and n = w + 8.
    {
        int w = tid >> 5, l = tid & 31;
        #pragma unroll
        for (int rep = 0; rep < 2; rep++) {
            int n = w + rep * 8;
            float a1 = Ad[n];
            float a2 = a1 * a1, a4 = a2 * a2, a8 = a4 * a4, a16 = a8 * a8;
            float h = Wp[0][n][l];
            float v;
            v = __shfl_up_sync(0xffffffffu, h, 1);  if (l >= 1)  h = fmaf(a1,  v, h);
            v = __shfl_up_sync(0xffffffffu, h, 2);  if (l >= 2)  h = fmaf(a2,  v, h);
            v = __shfl_up_sync(0xffffffffu, h, 4);  if (l >= 4)  h = fmaf(a4,  v, h);
            v = __shfl_up_sync(0xffffffffu, h, 8);  if (l >= 8)  h = fmaf(a8,  v, h);
            v = __shfl_up_sync(0xffffffffu, h, 16); if (l >= 16) h = fmaf(a16, v, h);
            float h31 = __shfl_sync(0xffffffffu, h, 31);
            Wp[0][n][l] = h;
            float g2 = Wp[0][n][l + 32];
            v = __shfl_up_sync(0xffffffffu, g2, 1);  if (l >= 1)  g2 = fmaf(a1,  v, g2);
            v = __shfl_up_sync(0xffffffffu, g2, 2);  if (l >= 2)  g2 = fmaf(a2,  v, g2);
            v = __shfl_up_sync(0xffffffffu, g2, 4);  if (l >= 4)  g2 = fmaf(a4,  v, g2);
            v = __shfl_up_sync(0xffffffffu, g2, 8);  if (l >= 8)  g2 = fmaf(a8,  v, g2);
            v = __shfl_up_sync(0xffffffffu, g2, 16); if (l >= 16) g2 = fmaf(a16, v, g2);
            float al = a1;
            if (l & 1)  al *= a1;
            if (l & 2)  al *= a2;
            if (l & 4)  al *= a4;
            if (l & 8)  al *= a8;
            if (l & 16) al *= a16;
            g2 = fmaf(al, h31, g2);
            Wp[0][n][l + 32] = g2;
            if (l == 31) g_hend[(b * Cn + c) * Nn + n] = g2;
        }
    }
    __syncthreads();

    // Copy-out H in [t][n] order (coalesced global).
    size_t base = ((size_t)(b * Cn + c)) * Ln * Nn;
    #pragma unroll
    for (int k = 0; k < 4; k++) {
        int i = tid + k * 256;
        int tt = i >> 4, n = i & 15;
        g_H[base + i] = Wp[0][n][tt];
    }
}

// ---------------------------------------------------------------------------
// Phase 2: scan across chunks. One block, 256 threads = (b, n).
// ---------------------------------------------------------------------------
__global__ __launch_bounds__(256) void s4_phase2(const float* __restrict__ A) {
    int tid = threadIdx.x;
    int b = tid >> 4, n = tid & 15;
    float a = (float)exp(-(double)DTc * fabs((double)A[n]));
    float aL = a;
    #pragma unroll
    for (int i = 0; i < 6; i++) aL *= aL;   // a^64

    float he[Cn];
    #pragma unroll
    for (int c = 0; c < Cn; c++) he[c] = g_hend[(b * Cn + c) * Nn + n];
    float s = 0.f;
    #pragma unroll
    for (int c = 0; c < Cn; c++) {
        g_hstart[(b * Cn + c) * Nn + n] = s;
        s = fmaf(aL, s, he[c]);
    }
}

// ---------------------------------------------------------------------------
// Phase 3: per (batch, chunk). cp.async-stage x while loading/correcting H,
// then GEMM2 (fp32 FMA, d & d+128, t-halves, smem u), LayerNorm, write out.
// ---------------------------------------------------------------------------
__global__ __launch_bounds__(256, 3) void s4_phase3(const float* __restrict__ x,
                                                    const float* __restrict__ A,
                                                    const float* __restrict__ Cm,
                                                    const float* __restrict__ Dv,
                                                    const float* __restrict__ gamma,
                                                    const float* __restrict__ beta,
                                                    float* __restrict__ out) {
    extern __shared__ float smem[];
    float (*Ys)[XS] = (float(*)[XS])smem;                    // 64 x 260 (u, then y)
    float (*Ht)[Nn] = (float(*)[Nn])(smem + Ln * XS);        // 64 x 16 [t][n]

    int blk = blockIdx.x;
    int b = blk / Cn, c = blk % Cn;
    int tid = threadIdx.x;

    // Async-stage x chunk.
    const float4* xg = (const float4*)(x + ((size_t)b * Sn + (size_t)c * Ln) * Dn);
    #pragma unroll
    for (int k = 0; k < 16; k++) {
        int i4 = tid + k * 256;
        int t = i4 >> 6, d4 = i4 & 63;
        cpasync16(&Ys[t][d4 * 4], xg + i4);
    }
    cpasync_commit();

    // Load local H ([t][n]): one float4 per thread.
    {
        const float4* hg = (const float4*)(g_H + ((size_t)(b * Cn + c)) * Ln * Nn);
        ((float4*)&Ht[0][0])[tid] = hg[tid];
    }
    __syncthreads();

    // Parallel correction: all 1024 (t,n) cells, 4 per thread (same n).
    {
        int n  = tid & 15;
        int tt = tid >> 4;
        float a1 = (float)exp(-(double)DTc * fabs((double)A[n]));
        float s  = g_hstart[(b * Cn + c) * Nn + n];
        float a2 = a1 * a1, a4 = a2 * a2, a8 = a4 * a4;
        float a16 = a8 * a8, a32 = a16 * a16;
        #pragma unroll
        for (int k = 0; k < 4; k++) {
            int t = tt + k * 16;
            int e = t + 1;
            float p = 1.f;
            if (e & 1)  p *= a1;
            if (e & 2)  p *= a2;
            if (e & 4)  p *= a4;
            if (e & 8)  p *= a8;
            if (e & 16) p *= a16;
            if (e & 32) p *= a32;
            if (e == 64) p = a32 * a32;
            float vv = fmaf(p, s, Ht[t][n]);
            vv = fminf(fmaxf(vv, -10.f), 10.f);
            Ht[t][n] = vv;
        }
    }
    cpasync_wait0();
    __syncthreads();

    // GEMM2: thread = (d, t-half); u from staged smem, y in-place.
    int d  = tid & 127;
    int t0 = (tid >> 7) * 32;
    const float4* cmp = (const float4*)(Cm + d * Nn);
    const float4* emp = (const float4*)(Cm + (d + 128) * Nn);
    float4 c0 = cmp[0], c1 = cmp[1], c2 = cmp[2], c3 = cmp[3];
    float4 e0 = emp[0], e1 = emp[1], e2 = emp[2], e3 = emp[3];
    float dv0 = Dv[d], dv1 = Dv[d + 128];

    const float4* hp = (const float4*)&Ht[t0][0];
    float4 h0 = hp[0], h1 = hp[1], h2 = hp[2], h3 = hp[3];
    #pragma unroll 4
    for (int t = 0; t < 32; t++) {
        int tn = (t < 31) ? t + 1 : 31;
        float4 h0n = hp[4 * tn + 0], h1n = hp[4 * tn + 1];
        float4 h2n = hp[4 * tn + 2], h3n = hp[4 * tn + 3];
        float u0 = Ys[t0 + t][d], u1 = Ys[t0 + t][d + 128];

        float acc = u0 * dv0;
        acc = fmaf(c0.x, h0.x, acc); acc = fmaf(c0.y, h0.y, acc);
        acc = fmaf(c0.z, h0.z, acc); acc = fmaf(c0.w, h0.w, acc);
        acc = fmaf(c1.x, h1.x, acc); acc = fmaf(c1.y, h1.y, acc);
        acc = fmaf(c1.z, h1.z, acc); acc = fmaf(c1.w, h1.w, acc);
        acc = fmaf(c2.x, h2.x, acc); acc = fmaf(c2.y, h2.y, acc);
        acc = fmaf(c2.z, h2.z, acc); acc = fmaf(c2.w, h2.w, acc);
        acc = fmaf(c3.x, h3.x, acc); acc = fmaf(c3.y, h3.y, acc);
        acc = fmaf(c3.z, h3.z, acc); acc = fmaf(c3.w, h3.w, acc);
        acc = fminf(fmaxf(acc, -10.f), 10.f);

        float acd = u1 * dv1;
        acd = fmaf(e0.x, h0.x, acd); acd = fmaf(e0.y, h0.y, acd);
        acd = fmaf(e0.z, h0.z, acd); acd = fmaf(e0.w, h0.w, acd);
        acd = fmaf(e1.x, h1.x, acd); acd = fmaf(e1.y, h1.y, acd);
        acd = fmaf(e1.z, h1.z, acd); acd = fmaf(e1.w, h1.w, acd);
        acd = fmaf(e2.x, h2.x, acd); acd = fmaf(e2.y, h2.y, acd);
        acd = fmaf(e2.z, h2.z, acd); acd = fmaf(e2.w, h2.w, acd);
        acd = fmaf(e3.x, h3.x, acd); acd = fmaf(e3.y, h3.y, acd);
        acd = fmaf(e3.z, h3.z, acd); acd = fmaf(e3.w, h3.w, acd);
        acd = fminf(fmaxf(acd, -10.f), 10.f);

        Ys[t0 + t][d] = acc;
        Ys[t0 + t][d + 128] = acd;
        h0 = h0n; h1 = h1n; h2 = h2n; h3 = h3n;
    }
    __syncthreads();

    // LayerNorm: one warp per 8 rows.
    int w = tid >> 5, lane = tid & 31;
    float g[8], bt[8];
    #pragma unroll
    for (int k = 0; k < 8; k++) {
        g[k]  = gamma[lane + 32 * k];
        bt[k] = beta[lane + 32 * k];
    }
    #pragma unroll
    for (int r = 0; r < 8; r++) {
        int t = w * 8 + r;
        float yv[8];
        float s1 = 0.f, s2 = 0.f;
        #pragma unroll
        for (int k = 0; k < 8; k++) {
            float y = Ys[t][lane + 32 * k];
            yv[k] = y;
            s1 += y;
            s2 = fmaf(y, y, s2);
        }
        #pragma unroll
        for (int off = 16; off > 0; off >>= 1) {
            s1 += __shfl_xor_sync(0xffffffffu, s1, off);
            s2 += __shfl_xor_sync(0xffffffffu, s2, off);
        }
        float mu  = s1 * (1.f / Dn);
        float var = s2 * (1.f / Dn) - mu * mu;
        float rs  = rsqrtf(var + EPSc);
        float* orow = out + ((size_t)b * Sn + (size_t)(c * Ln + t)) * Dn;
        #pragma unroll
        for (int k = 0; k < 8; k++) {
            orow[lane + 32 * k] = fmaf((yv[k] - mu) * rs, g[k], bt[k]);
        }
    }
}

extern "C" void kernel_launch(void* const* d_in, const int* in_sizes, int n_in,
                              void* d_out, int out_size) {
    (void)in_sizes; (void)n_in; (void)out_size;
    const float* x     = (const float*)d_in[0];
    const float* A     = (const float*)d_in[1];
    const float* Bm    = (const float*)d_in[2];
    const float* Cm    = (const float*)d_in[3];
    const float* Dv    = (const float*)d_in[4];
    const float* gamma = (const float*)d_in[5];
    const float* beta  = (const float*)d_in[6];
    float* out = (float*)d_out;

    const int smem1 = (Ln * XS + Dn * BS + 4 * Nn * WS + Nn) * 4;   // ~102 KB
    const int smem3 = (Ln * XS + Ln * Nn) * 4;                      // ~70.7 KB
    cudaFuncSetAttribute(s4_phase1, cudaFuncAttributeMaxDynamicSharedMemorySize, smem1);
    cudaFuncSetAttribute(s4_phase3, cudaFuncAttributeMaxDynamicSharedMemorySize, smem3);

    s4_phase1<<<Bn * Cn, 256, smem1>>>(x, A, Bm);
    s4_phase2<<<1, 256>>>(A);
    s4_phase3<<<Bn * Cn, 256, smem3>>>(x, A, Cm, Dv, gamma, beta, out);
}